// round 11
// baseline (speedup 1.0000x reference)
#include <cuda_runtime.h>
#include <cstdint>

#define Bb 2
#define Nn 2048
#define Mm 64
#define Ff 128
#define H1 64
#define H2 64
#define TILE 8          // atoms per MLP block
#define MLP_THREADS 256 // 4 pairs x 64 neurons
#define FBLK 384        // force threads per atom block

// scratch (allocation-free rule: __device__ globals; zero-initialized)
__device__ float g_buf[Bb * Nn * Ff];   // input-gradient per atom  [B*N, F]
__device__ float Ei_buf[Bb * Nn];       // per-atom energy
__device__ float g_zero[Ff];            // stays all-zero (pad-neighbor source)

__device__ __forceinline__ float sigmoidf(float z) {
    return 1.f / (1.f + __expf(-z));
}

__device__ __forceinline__ void cp_async16(void* dst_smem, const void* src_gmem) {
    unsigned int d = (unsigned int)__cvta_generic_to_shared(dst_smem);
    asm volatile("cp.async.ca.shared.global [%0], [%1], 16;" :: "r"(d), "l"(src_gmem));
}

// ---------------------------------------------------------------------------
// Kernel 1: batched per-atom MLP forward + analytic input gradient.
// 256 threads / 8 atoms; 2 atoms per thread. float4 activation broadcasts;
// weights padded-transposed (stride 65, conflict-free both directions).
// ---------------------------------------------------------------------------
__global__ __launch_bounds__(MLP_THREADS) void mlp_kernel(
    const float* __restrict__ image,
    const float* __restrict__ W0,     // [H1, F]   row-major
    const float* __restrict__ W1,     // [H2, H1]  row-major
    const float* __restrict__ Wout,   // [1, H2]
    int base_atom)
{
    extern __shared__ float sm[];
    float* W0T   = sm;                      // [F][65]
    float* W1T   = W0T + Ff * 65;           // [H1][65]
    float* WoS   = W1T + H1 * 65;           // [64]
    float* xs    = WoS + 64;                // [TILE][128]
    float* h0s   = xs  + TILE * Ff;         // [TILE][64]
    float* t1s   = h0s + TILE * H1;         // [TILE][64]
    float* t0s   = t1s + TILE * H2;         // [TILE][64]
    float* ePart = t0s + TILE * H1;         // [TILE][2]

    const int t    = threadIdx.x;
    const int base = base_atom + blockIdx.x * TILE;
    const int p    = t >> 6;
    const int n    = t & 63;
    const int a0   = 2 * p, a1 = 2 * p + 1;

    for (int i = t; i < H1 * Ff; i += MLP_THREADS) {
        int r = i >> 7, f = i & 127;
        W0T[f * 65 + r] = W0[i];
    }
    for (int i = t; i < H2 * H1; i += MLP_THREADS) {
        int j = i >> 6, k = i & 63;
        W1T[k * 65 + j] = W1[i];
    }
    if (t < H2) WoS[t] = Wout[t];
    for (int i = t; i < TILE * Ff; i += MLP_THREADS)
        xs[i] = image[(size_t)base * Ff + i];
    __syncthreads();

    // phase 1: h0 = sigmoid(x @ W0^T)
    {
        const float4* X0 = (const float4*)(xs + a0 * Ff);
        const float4* X1 = (const float4*)(xs + a1 * Ff);
        float s0a = 0.f, s0b = 0.f, s1a = 0.f, s1b = 0.f;
#pragma unroll
        for (int f4 = 0; f4 < Ff / 4; f4++) {
            float4 xa = X0[f4];
            float4 xb = X1[f4];
            const int f = f4 * 4;
            float w0 = W0T[(f + 0) * 65 + n];
            float w1 = W0T[(f + 1) * 65 + n];
            float w2 = W0T[(f + 2) * 65 + n];
            float w3 = W0T[(f + 3) * 65 + n];
            s0a = fmaf(xa.x, w0, s0a); s0b = fmaf(xa.y, w1, s0b);
            s0a = fmaf(xa.z, w2, s0a); s0b = fmaf(xa.w, w3, s0b);
            s1a = fmaf(xb.x, w0, s1a); s1b = fmaf(xb.y, w1, s1b);
            s1a = fmaf(xb.z, w2, s1a); s1b = fmaf(xb.w, w3, s1b);
        }
        h0s[a0 * 64 + n] = sigmoidf(s0a + s0b);
        h0s[a1 * 64 + n] = sigmoidf(s1a + s1b);
    }
    __syncthreads();

    // phase 2: h1, t1 = h1(1-h1)*Wout, Ei partials
    {
        const float4* Ha = (const float4*)(h0s + a0 * 64);
        const float4* Hb = (const float4*)(h0s + a1 * 64);
        float s0a = 0.f, s0b = 0.f, s1a = 0.f, s1b = 0.f;
#pragma unroll
        for (int k4 = 0; k4 < H1 / 4; k4++) {
            float4 ha = Ha[k4];
            float4 hb = Hb[k4];
            const int k = k4 * 4;
            float w0 = W1T[(k + 0) * 65 + n];
            float w1 = W1T[(k + 1) * 65 + n];
            float w2 = W1T[(k + 2) * 65 + n];
            float w3 = W1T[(k + 3) * 65 + n];
            s0a = fmaf(ha.x, w0, s0a); s0b = fmaf(ha.y, w1, s0b);
            s0a = fmaf(ha.z, w2, s0a); s0b = fmaf(ha.w, w3, s0b);
            s1a = fmaf(hb.x, w0, s1a); s1b = fmaf(hb.y, w1, s1b);
            s1a = fmaf(hb.z, w2, s1a); s1b = fmaf(hb.w, w3, s1b);
        }
        float wo   = WoS[n];
        float h1_0 = sigmoidf(s0a + s0b);
        float h1_1 = sigmoidf(s1a + s1b);
        t1s[a0 * 64 + n] = h1_0 * (1.f - h1_0) * wo;
        t1s[a1 * 64 + n] = h1_1 * (1.f - h1_1) * wo;
        float e0 = h1_0 * wo, e1 = h1_1 * wo;
#pragma unroll
        for (int off = 16; off > 0; off >>= 1) {
            e0 += __shfl_down_sync(0xffffffffu, e0, off);
            e1 += __shfl_down_sync(0xffffffffu, e1, off);
        }
        if ((n & 31) == 0) {
            int half = n >> 5;
            ePart[a0 * 2 + half] = e0;
            ePart[a1 * 2 + half] = e1;
        }
    }
    __syncthreads();

    // phase 3: g1 = t1 @ W1 ; t0 = h0(1-h0)*g1
    {
        const float4* Ta = (const float4*)(t1s + a0 * 64);
        const float4* Tb = (const float4*)(t1s + a1 * 64);
        float s0a = 0.f, s0b = 0.f, s1a = 0.f, s1b = 0.f;
#pragma unroll
        for (int j4 = 0; j4 < H2 / 4; j4++) {
            float4 ta = Ta[j4];
            float4 tb = Tb[j4];
            const int j = j4 * 4;
            float w0 = W1T[n * 65 + j + 0];
            float w1 = W1T[n * 65 + j + 1];
            float w2 = W1T[n * 65 + j + 2];
            float w3 = W1T[n * 65 + j + 3];
            s0a = fmaf(ta.x, w0, s0a); s0b = fmaf(ta.y, w1, s0b);
            s0a = fmaf(ta.z, w2, s0a); s0b = fmaf(ta.w, w3, s0b);
            s1a = fmaf(tb.x, w0, s1a); s1b = fmaf(tb.y, w1, s1b);
            s1a = fmaf(tb.z, w2, s1a); s1b = fmaf(tb.w, w3, s1b);
        }
        float h00 = h0s[a0 * 64 + n];
        float h01 = h0s[a1 * 64 + n];
        t0s[a0 * 64 + n] = h00 * (1.f - h00) * (s0a + s0b);
        t0s[a1 * 64 + n] = h01 * (1.f - h01) * (s1a + s1b);
        if (n == 0) {
            Ei_buf[base + a0] = ePart[a0 * 2] + ePart[a0 * 2 + 1];
            Ei_buf[base + a1] = ePart[a1 * 2] + ePart[a1 * 2 + 1];
        }
    }
    __syncthreads();

    // phase 4: g[f] = sum_k t0[k] * W0[k][f]
    {
        const int f0 = n, f1 = n + 64;
        const float4* Pa = (const float4*)(t0s + a0 * 64);
        const float4* Pb = (const float4*)(t0s + a1 * 64);
        float g00 = 0.f, g01 = 0.f, g10 = 0.f, g11 = 0.f;
#pragma unroll
        for (int k4 = 0; k4 < H1 / 4; k4++) {
            float4 ta = Pa[k4];
            float4 tb = Pb[k4];
            const int k = k4 * 4;
#pragma unroll
            for (int u = 0; u < 4; u++) {
                float w0 = W0T[f0 * 65 + k + u];
                float w1 = W0T[f1 * 65 + k + u];
                float va = (u == 0) ? ta.x : (u == 1) ? ta.y : (u == 2) ? ta.z : ta.w;
                float vb = (u == 0) ? tb.x : (u == 1) ? tb.y : (u == 2) ? tb.z : tb.w;
                g00 = fmaf(va, w0, g00);
                g01 = fmaf(va, w1, g01);
                g10 = fmaf(vb, w0, g10);
                g11 = fmaf(vb, w1, g11);
            }
        }
        float* go0 = g_buf + (size_t)(base + a0) * Ff;
        float* go1 = g_buf + (size_t)(base + a1) * Ff;
        go0[f0] = g00; go0[f1] = g01;
        go1[f0] = g10; go1[f1] = g11;
    }
}

// ---------------------------------------------------------------------------
// Kernel 2: force — group-local gather with named barriers.
// Group g = threads [96g, 96g+96) (3 whole warps) reads ONLY rows m ≡ g
// (mod 4). Each group gathers its own 16 rows via cp.async, waits on its own
// commit group, and syncs with a 96-thread named barrier (id g+1). No
// block-wide barrier until the final reduction: 16-deep dfeat MLP restored,
// convoy width 3 warps, and the 4 groups de-phase so one group's DRAM stream
// covers another's gather drain. Lane l always writes f4 = l (conflict-free).
// ---------------------------------------------------------------------------
__global__ __launch_bounds__(FBLK) void force_kernel(
    const int*   __restrict__ neighbor,   // [B*N, M]
    const float* __restrict__ dfeat,      // [B*N, M, F, 3]
    float*       __restrict__ out_force,  // [B*N, 3]
    int base_atom)
{
    const int atom = base_atom + blockIdx.x;
    const int b    = atom >> 11;            // N = 2048
    const int t    = threadIdx.x;
    const int gid  = t / 96;                 // row group 0..3
    const int tig  = t % 96;                 // thread in group

    __shared__ float sg[Mm * Ff];             // 32 KB gathered+masked g rows
    __shared__ float wsum[12][3];

    // ---- group-local gather: rows m = gid + 4k, k = 0..15 ----
    {
        float4*       sg4 = (float4*)sg;
        const float4* g4  = (const float4*)g_buf;
        const float4* z4  = (const float4*)g_zero;
        const int*    nb  = neighbor + atom * Mm;
        for (int j = tig; j < 512; j += 96) {   // 512 float4 per group
            int k  = j >> 5;                    // 0..15
            int f4 = j & 31;                    // == lane (conflict-free)
            int m  = gid + 4 * k;
            int nei = __ldg(nb + m);
            const float4* src = (nei > 0)
                ? g4 + ((size_t)(b * Nn + nei - 1)) * (Ff / 4) + f4
                : z4 + f4;
            cp_async16(sg4 + m * (Ff / 4) + f4, src);
        }
        asm volatile("cp.async.commit_group;");
        asm volatile("cp.async.wait_group 0;" ::: "memory");
        asm volatile("bar.sync %0, 96;" :: "r"(gid + 1) : "memory");
    }

    const int r4  = tig;                      // loop-invariant per thread
    const int m0  = gid;
    const int cse = r4 % 3;
    const int f0  = (4 * r4) / 3;             // 0..126

    const float4* dp = (const float4*)(dfeat + (size_t)atom * (Mm * Ff * 3)) + t;

    float A0 = 0.f, A1 = 0.f, A2 = 0.f;       // A_k holds c = (cse+k)%3
#pragma unroll
    for (int it = 0; it < 16; it++) {
        const int m = m0 + 4 * it;
        float4 v = __ldg(dp + (size_t)it * 384);
        float s0 = sg[m * Ff + f0];
        float s1 = sg[m * Ff + f0 + 1];
        float sy = (cse == 2) ? s1 : s0;
        float sz = (cse == 0) ? s0 : s1;
        A0 = fmaf(v.x, s0, A0);
        A1 = fmaf(v.y, sy, A1);
        A2 = fmaf(v.z, sz, A2);
        A0 = fmaf(v.w, s1, A0);
    }
    float c0 = (cse == 0) ? A0 : (cse == 1) ? A2 : A1;
    float c1 = (cse == 0) ? A1 : (cse == 1) ? A0 : A2;
    float c2 = (cse == 0) ? A2 : (cse == 1) ? A1 : A0;

#pragma unroll
    for (int off = 16; off > 0; off >>= 1) {
        c0 += __shfl_down_sync(0xffffffffu, c0, off);
        c1 += __shfl_down_sync(0xffffffffu, c1, off);
        c2 += __shfl_down_sync(0xffffffffu, c2, off);
    }
    const int w = t >> 5;
    if ((t & 31) == 0) { wsum[w][0] = c0; wsum[w][1] = c1; wsum[w][2] = c2; }
    __syncthreads();

    if (t < 3) {
        float s = 0.f;
#pragma unroll
        for (int w2 = 0; w2 < 12; w2++) s += wsum[w2][t];
        out_force[atom * 3 + t] = s * 1e10f;
    }
}

// ---------------------------------------------------------------------------
// Kernel 3: deterministic Etot = sum_n Ei  (double accumulation)
// ---------------------------------------------------------------------------
__global__ __launch_bounds__(256) void etot_kernel(float* __restrict__ out)
{
    const int b = blockIdx.x;
    const int t = threadIdx.x;
    __shared__ double sd[256];

    double s = 0.0;
    for (int n = t; n < Nn; n += 256) s += (double)Ei_buf[b * Nn + n];
    sd[t] = s;
    __syncthreads();
#pragma unroll
    for (int k = 128; k > 0; k >>= 1) {
        if (t < k) sd[t] += sd[t + k];
        __syncthreads();
    }
    if (t == 0) out[b] = (float)sd[0];
}

// ---------------------------------------------------------------------------
// Launch: fork-join; force launches on separate side streams (b1 backfills
// b0's draining wave); mlp_b1 + etot hide behind force_b0.
// ---------------------------------------------------------------------------
extern "C" void kernel_launch(void* const* d_in, const int* in_sizes, int n_in,
                              void* d_out, int out_size)
{
    const float* image    = (const float*)d_in[0];
    const float* dfeat    = (const float*)d_in[1];
    const int*   neighbor = (const int*)  d_in[2];
    const float* W0       = (const float*)d_in[5];
    const float* W1       = (const float*)d_in[6];
    const float* Wout     = (const float*)d_in[7];
    float* out = (float*)d_out;

    const int mlp_smem = (Ff * 65 + H1 * 65 + 64 + TILE * Ff + 3 * TILE * 64 + 2 * TILE)
                       * (int)sizeof(float);

    static cudaStream_t s2 = nullptr, s3 = nullptr;
    static cudaEvent_t  e0, e1, eD0, eD1;
    if (!s2) {
        cudaStreamCreateWithFlags(&s2, cudaStreamNonBlocking);
        cudaStreamCreateWithFlags(&s3, cudaStreamNonBlocking);
        cudaEventCreateWithFlags(&e0,  cudaEventDisableTiming);
        cudaEventCreateWithFlags(&e1,  cudaEventDisableTiming);
        cudaEventCreateWithFlags(&eD0, cudaEventDisableTiming);
        cudaEventCreateWithFlags(&eD1, cudaEventDisableTiming);
        cudaFuncSetAttribute(mlp_kernel, cudaFuncAttributeMaxDynamicSharedMemorySize, mlp_smem);
    }

    // main stream (0): mlp b0 -> e0 -> mlp b1 -> e1 -> etot -> join
    mlp_kernel<<<Nn / TILE, MLP_THREADS, mlp_smem>>>(image, W0, W1, Wout, 0);
    cudaEventRecord(e0, 0);
    mlp_kernel<<<Nn / TILE, MLP_THREADS, mlp_smem>>>(image, W0, W1, Wout, Nn);
    cudaEventRecord(e1, 0);
    etot_kernel<<<Bb, 256>>>(out);

    // side stream s2: force b0 after mlp b0
    cudaStreamWaitEvent(s2, e0, 0);
    force_kernel<<<Nn, FBLK, 0, s2>>>(neighbor, dfeat, out + 2, 0);
    cudaEventRecord(eD0, s2);

    // side stream s3: force b1 after mlp b1 (backfills force b0's tail)
    cudaStreamWaitEvent(s3, e1, 0);
    force_kernel<<<Nn, FBLK, 0, s3>>>(neighbor, dfeat, out + 2, Nn);
    cudaEventRecord(eD1, s3);

    cudaStreamWaitEvent(0, eD0, 0);
    cudaStreamWaitEvent(0, eD1, 0);
}

// round 12
// speedup vs baseline: 1.0476x; 1.0476x over previous
#include <cuda_runtime.h>
#include <cstdint>

#define Bb 2
#define Nn 2048
#define Mm 64
#define Ff 128
#define H1 64
#define H2 64
#define TILE 8          // atoms per MLP block
#define MLP_THREADS 256 // 4 pairs x 64 neurons
#define FBLK 384        // force threads per atom block

// scratch (allocation-free rule: __device__ globals; zero-initialized)
__device__ float g_buf[Bb * Nn * Ff];   // input-gradient per atom  [B*N, F]
__device__ float Ei_buf[Bb * Nn];       // per-atom energy
__device__ float g_zero[Ff];            // stays all-zero (pad-neighbor source)

__device__ __forceinline__ float sigmoidf(float z) {
    return 1.f / (1.f + __expf(-z));
}

__device__ __forceinline__ void cp_async16(void* dst_smem, const void* src_gmem) {
    unsigned int d = (unsigned int)__cvta_generic_to_shared(dst_smem);
    asm volatile("cp.async.ca.shared.global [%0], [%1], 16;" :: "r"(d), "l"(src_gmem));
}

__device__ __forceinline__ float4 ldcs4(const float4* p) {
    float4 v;
    asm volatile("ld.global.cs.v4.f32 {%0,%1,%2,%3}, [%4];"
                 : "=f"(v.x), "=f"(v.y), "=f"(v.z), "=f"(v.w) : "l"(p));
    return v;
}

// ---------------------------------------------------------------------------
// Kernel 1: batched per-atom MLP forward + analytic input gradient.
// 256 threads / 8 atoms; 2 atoms per thread. float4 activation broadcasts;
// weights padded-transposed (stride 65, conflict-free both directions).
// Single launch covers BOTH batches (grid = Bb*Nn/TILE).
// ---------------------------------------------------------------------------
__global__ __launch_bounds__(MLP_THREADS) void mlp_kernel(
    const float* __restrict__ image,
    const float* __restrict__ W0,     // [H1, F]   row-major
    const float* __restrict__ W1,     // [H2, H1]  row-major
    const float* __restrict__ Wout)   // [1, H2]
{
    extern __shared__ float sm[];
    float* W0T   = sm;                      // [F][65]
    float* W1T   = W0T + Ff * 65;           // [H1][65]
    float* WoS   = W1T + H1 * 65;           // [64]
    float* xs    = WoS + 64;                // [TILE][128]
    float* h0s   = xs  + TILE * Ff;         // [TILE][64]
    float* t1s   = h0s + TILE * H1;         // [TILE][64]
    float* t0s   = t1s + TILE * H2;         // [TILE][64]
    float* ePart = t0s + TILE * H1;         // [TILE][2]

    const int t    = threadIdx.x;
    const int base = blockIdx.x * TILE;
    const int p    = t >> 6;
    const int n    = t & 63;
    const int a0   = 2 * p, a1 = 2 * p + 1;

    for (int i = t; i < H1 * Ff; i += MLP_THREADS) {
        int r = i >> 7, f = i & 127;
        W0T[f * 65 + r] = W0[i];
    }
    for (int i = t; i < H2 * H1; i += MLP_THREADS) {
        int j = i >> 6, k = i & 63;
        W1T[k * 65 + j] = W1[i];
    }
    if (t < H2) WoS[t] = Wout[t];
    for (int i = t; i < TILE * Ff; i += MLP_THREADS)
        xs[i] = image[(size_t)base * Ff + i];
    __syncthreads();

    // phase 1: h0 = sigmoid(x @ W0^T)
    {
        const float4* X0 = (const float4*)(xs + a0 * Ff);
        const float4* X1 = (const float4*)(xs + a1 * Ff);
        float s0a = 0.f, s0b = 0.f, s1a = 0.f, s1b = 0.f;
#pragma unroll
        for (int f4 = 0; f4 < Ff / 4; f4++) {
            float4 xa = X0[f4];
            float4 xb = X1[f4];
            const int f = f4 * 4;
            float w0 = W0T[(f + 0) * 65 + n];
            float w1 = W0T[(f + 1) * 65 + n];
            float w2 = W0T[(f + 2) * 65 + n];
            float w3 = W0T[(f + 3) * 65 + n];
            s0a = fmaf(xa.x, w0, s0a); s0b = fmaf(xa.y, w1, s0b);
            s0a = fmaf(xa.z, w2, s0a); s0b = fmaf(xa.w, w3, s0b);
            s1a = fmaf(xb.x, w0, s1a); s1b = fmaf(xb.y, w1, s1b);
            s1a = fmaf(xb.z, w2, s1a); s1b = fmaf(xb.w, w3, s1b);
        }
        h0s[a0 * 64 + n] = sigmoidf(s0a + s0b);
        h0s[a1 * 64 + n] = sigmoidf(s1a + s1b);
    }
    __syncthreads();

    // phase 2: h1, t1 = h1(1-h1)*Wout, Ei partials
    {
        const float4* Ha = (const float4*)(h0s + a0 * 64);
        const float4* Hb = (const float4*)(h0s + a1 * 64);
        float s0a = 0.f, s0b = 0.f, s1a = 0.f, s1b = 0.f;
#pragma unroll
        for (int k4 = 0; k4 < H1 / 4; k4++) {
            float4 ha = Ha[k4];
            float4 hb = Hb[k4];
            const int k = k4 * 4;
            float w0 = W1T[(k + 0) * 65 + n];
            float w1 = W1T[(k + 1) * 65 + n];
            float w2 = W1T[(k + 2) * 65 + n];
            float w3 = W1T[(k + 3) * 65 + n];
            s0a = fmaf(ha.x, w0, s0a); s0b = fmaf(ha.y, w1, s0b);
            s0a = fmaf(ha.z, w2, s0a); s0b = fmaf(ha.w, w3, s0b);
            s1a = fmaf(hb.x, w0, s1a); s1b = fmaf(hb.y, w1, s1b);
            s1a = fmaf(hb.z, w2, s1a); s1b = fmaf(hb.w, w3, s1b);
        }
        float wo   = WoS[n];
        float h1_0 = sigmoidf(s0a + s0b);
        float h1_1 = sigmoidf(s1a + s1b);
        t1s[a0 * 64 + n] = h1_0 * (1.f - h1_0) * wo;
        t1s[a1 * 64 + n] = h1_1 * (1.f - h1_1) * wo;
        float e0 = h1_0 * wo, e1 = h1_1 * wo;
#pragma unroll
        for (int off = 16; off > 0; off >>= 1) {
            e0 += __shfl_down_sync(0xffffffffu, e0, off);
            e1 += __shfl_down_sync(0xffffffffu, e1, off);
        }
        if ((n & 31) == 0) {
            int half = n >> 5;
            ePart[a0 * 2 + half] = e0;
            ePart[a1 * 2 + half] = e1;
        }
    }
    __syncthreads();

    // phase 3: g1 = t1 @ W1 ; t0 = h0(1-h0)*g1
    {
        const float4* Ta = (const float4*)(t1s + a0 * 64);
        const float4* Tb = (const float4*)(t1s + a1 * 64);
        float s0a = 0.f, s0b = 0.f, s1a = 0.f, s1b = 0.f;
#pragma unroll
        for (int j4 = 0; j4 < H2 / 4; j4++) {
            float4 ta = Ta[j4];
            float4 tb = Tb[j4];
            const int j = j4 * 4;
            float w0 = W1T[n * 65 + j + 0];
            float w1 = W1T[n * 65 + j + 1];
            float w2 = W1T[n * 65 + j + 2];
            float w3 = W1T[n * 65 + j + 3];
            s0a = fmaf(ta.x, w0, s0a); s0b = fmaf(ta.y, w1, s0b);
            s0a = fmaf(ta.z, w2, s0a); s0b = fmaf(ta.w, w3, s0b);
            s1a = fmaf(tb.x, w0, s1a); s1b = fmaf(tb.y, w1, s1b);
            s1a = fmaf(tb.z, w2, s1a); s1b = fmaf(tb.w, w3, s1b);
        }
        float h00 = h0s[a0 * 64 + n];
        float h01 = h0s[a1 * 64 + n];
        t0s[a0 * 64 + n] = h00 * (1.f - h00) * (s0a + s0b);
        t0s[a1 * 64 + n] = h01 * (1.f - h01) * (s1a + s1b);
        if (n == 0) {
            Ei_buf[base + a0] = ePart[a0 * 2] + ePart[a0 * 2 + 1];
            Ei_buf[base + a1] = ePart[a1 * 2] + ePart[a1 * 2 + 1];
        }
    }
    __syncthreads();

    // phase 4: g[f] = sum_k t0[k] * W0[k][f]
    {
        const int f0 = n, f1 = n + 64;
        const float4* Pa = (const float4*)(t0s + a0 * 64);
        const float4* Pb = (const float4*)(t0s + a1 * 64);
        float g00 = 0.f, g01 = 0.f, g10 = 0.f, g11 = 0.f;
#pragma unroll
        for (int k4 = 0; k4 < H1 / 4; k4++) {
            float4 ta = Pa[k4];
            float4 tb = Pb[k4];
            const int k = k4 * 4;
#pragma unroll
            for (int u = 0; u < 4; u++) {
                float w0 = W0T[f0 * 65 + k + u];
                float w1 = W0T[f1 * 65 + k + u];
                float va = (u == 0) ? ta.x : (u == 1) ? ta.y : (u == 2) ? ta.z : ta.w;
                float vb = (u == 0) ? tb.x : (u == 1) ? tb.y : (u == 2) ? tb.z : tb.w;
                g00 = fmaf(va, w0, g00);
                g01 = fmaf(va, w1, g01);
                g10 = fmaf(vb, w0, g10);
                g11 = fmaf(vb, w1, g11);
            }
        }
        float* go0 = g_buf + (size_t)(base + a0) * Ff;
        float* go1 = g_buf + (size_t)(base + a1) * Ff;
        go0[f0] = g00; go0[f1] = g01;
        go1[f0] = g10; go1[f1] = g11;
    }
}

// ---------------------------------------------------------------------------
// Kernel 2: force — R10 chunked-gather pipeline (best measured), single
// launch over all B*N atoms. Gather issued as 4 cp.async commit groups
// (16 rows each); stream loop consumes chunk-by-chunk with progressive
// wait_group. dfeat loads use ld.global.cs (evict-first: 402MB read-once
// stream must not evict the L2-resident g_buf that gathers depend on).
// ---------------------------------------------------------------------------
__global__ __launch_bounds__(FBLK) void force_kernel(
    const int*   __restrict__ neighbor,   // [B*N, M]
    const float* __restrict__ dfeat,      // [B*N, M, F, 3]
    float*       __restrict__ out_force)  // [B*N, 3]
{
    const int atom = blockIdx.x;
    const int b    = atom >> 11;            // N = 2048
    const int t    = threadIdx.x;

    __shared__ float sg[Mm * Ff];            // 32 KB gathered+masked g rows
    __shared__ float wsum[12][3];

    // ---- issue 4 gather chunks (16 rows = 512 float4 each) ----
    {
        float4*       sg4 = (float4*)sg;
        const float4* g4  = (const float4*)g_buf;
        const float4* z4  = (const float4*)g_zero;
        const int*    nb  = neighbor + atom * Mm;
#pragma unroll
        for (int c = 0; c < 4; c++) {
            for (int i = c * 512 + t; i < (c + 1) * 512; i += FBLK) {
                int m  = i >> 5;             // row 0..63
                int f4 = i & 31;
                int nei = __ldg(nb + m);
                const float4* src = (nei > 0)
                    ? g4 + ((size_t)(b * Nn + nei - 1)) * (Ff / 4) + f4
                    : z4 + f4;
                cp_async16(sg4 + i, src);
            }
            asm volatile("cp.async.commit_group;");
        }
    }

    const int r4  = t % 96;                  // loop-invariant per thread
    const int m0  = t / 96;                  // 0..3
    const int cse = r4 % 3;
    const int f0  = (4 * r4) / 3;            // 0..126

    const float4* dp = (const float4*)(dfeat + (size_t)atom * (Mm * Ff * 3)) + t;

    float A0 = 0.f, A1 = 0.f, A2 = 0.f;      // A_k holds c = (cse+k)%3
#pragma unroll
    for (int c = 0; c < 4; c++) {
        if (c == 0)      asm volatile("cp.async.wait_group 3;" ::: "memory");
        else if (c == 1) asm volatile("cp.async.wait_group 2;" ::: "memory");
        else if (c == 2) asm volatile("cp.async.wait_group 1;" ::: "memory");
        else             asm volatile("cp.async.wait_group 0;" ::: "memory");
        __syncthreads();
#pragma unroll
        for (int q = 0; q < 4; q++) {
            const int it = c * 4 + q;
            const int m  = m0 + 4 * it;      // m in [16c, 16c+16)
            float4 v = ldcs4(dp + (size_t)it * 384);
            float s0 = sg[m * Ff + f0];
            float s1 = sg[m * Ff + f0 + 1];
            float sy = (cse == 2) ? s1 : s0;
            float sz = (cse == 0) ? s0 : s1;
            A0 = fmaf(v.x, s0, A0);
            A1 = fmaf(v.y, sy, A1);
            A2 = fmaf(v.z, sz, A2);
            A0 = fmaf(v.w, s1, A0);
        }
    }
    float c0 = (cse == 0) ? A0 : (cse == 1) ? A2 : A1;
    float c1 = (cse == 0) ? A1 : (cse == 1) ? A0 : A2;
    float c2 = (cse == 0) ? A2 : (cse == 1) ? A1 : A0;

#pragma unroll
    for (int off = 16; off > 0; off >>= 1) {
        c0 += __shfl_down_sync(0xffffffffu, c0, off);
        c1 += __shfl_down_sync(0xffffffffu, c1, off);
        c2 += __shfl_down_sync(0xffffffffu, c2, off);
    }
    const int w = t >> 5;
    if ((t & 31) == 0) { wsum[w][0] = c0; wsum[w][1] = c1; wsum[w][2] = c2; }
    __syncthreads();

    if (t < 3) {
        float s = 0.f;
#pragma unroll
        for (int w2 = 0; w2 < 12; w2++) s += wsum[w2][t];
        out_force[atom * 3 + t] = s * 1e10f;
    }
}

// ---------------------------------------------------------------------------
// Kernel 3: deterministic Etot = sum_n Ei  (double accumulation)
// ---------------------------------------------------------------------------
__global__ __launch_bounds__(256) void etot_kernel(float* __restrict__ out)
{
    const int b = blockIdx.x;
    const int t = threadIdx.x;
    __shared__ double sd[256];

    double s = 0.0;
    for (int n = t; n < Nn; n += 256) s += (double)Ei_buf[b * Nn + n];
    sd[t] = s;
    __syncthreads();
#pragma unroll
    for (int k = 128; k > 0; k >>= 1) {
        if (t < k) sd[t] += sd[t + k];
        __syncthreads();
    }
    if (t == 0) out[b] = (float)sd[0];
}

// ---------------------------------------------------------------------------
// Launch: single mlp (both batches) -> single force (4096 blocks, one wave
// schedule); etot overlaps force on a side stream.
// ---------------------------------------------------------------------------
extern "C" void kernel_launch(void* const* d_in, const int* in_sizes, int n_in,
                              void* d_out, int out_size)
{
    const float* image    = (const float*)d_in[0];
    const float* dfeat    = (const float*)d_in[1];
    const int*   neighbor = (const int*)  d_in[2];
    const float* W0       = (const float*)d_in[5];
    const float* W1       = (const float*)d_in[6];
    const float* Wout     = (const float*)d_in[7];
    float* out = (float*)d_out;

    const int mlp_smem = (Ff * 65 + H1 * 65 + 64 + TILE * Ff + 3 * TILE * 64 + 2 * TILE)
                       * (int)sizeof(float);

    static cudaStream_t s2 = nullptr;
    static cudaEvent_t  e0, eE;
    if (!s2) {
        cudaStreamCreateWithFlags(&s2, cudaStreamNonBlocking);
        cudaEventCreateWithFlags(&e0, cudaEventDisableTiming);
        cudaEventCreateWithFlags(&eE, cudaEventDisableTiming);
        cudaFuncSetAttribute(mlp_kernel, cudaFuncAttributeMaxDynamicSharedMemorySize, mlp_smem);
    }

    // stream 0: mlp (both batches) -> force (all atoms)
    mlp_kernel<<<(Bb * Nn) / TILE, MLP_THREADS, mlp_smem>>>(image, W0, W1, Wout);
    cudaEventRecord(e0, 0);
    force_kernel<<<Bb * Nn, FBLK>>>(neighbor, dfeat, out + 2);

    // side stream: etot overlaps force
    cudaStreamWaitEvent(s2, e0, 0);
    etot_kernel<<<Bb, 256, 0, s2>>>(out);
    cudaEventRecord(eE, s2);

    cudaStreamWaitEvent(0, eE, 0);
}

// round 13
// speedup vs baseline: 1.0694x; 1.0209x over previous
#include <cuda_runtime.h>
#include <cstdint>

#define Bb 2
#define Nn 2048
#define Mm 64
#define Ff 128
#define H1 64
#define H2 64
#define TILE 8          // atoms per MLP block
#define MLP_THREADS 256 // 4 pairs x 64 neurons
#define FBLK 384        // force threads per atom block

// scratch (allocation-free rule: __device__ globals; zero-initialized)
__device__ float g_buf[Bb * Nn * Ff];   // input-gradient per atom  [B*N, F]
__device__ float Ei_buf[Bb * Nn];       // per-atom energy
__device__ float g_zero[Ff];            // stays all-zero (pad-neighbor source)

__device__ __forceinline__ float sigmoidf(float z) {
    return 1.f / (1.f + __expf(-z));
}

__device__ __forceinline__ void cp_async16(void* dst_smem, const void* src_gmem) {
    unsigned int d = (unsigned int)__cvta_generic_to_shared(dst_smem);
    asm volatile("cp.async.ca.shared.global [%0], [%1], 16;" :: "r"(d), "l"(src_gmem));
}

__device__ __forceinline__ float4 ldcs4(const float4* p) {
    float4 v;
    asm volatile("ld.global.cs.v4.f32 {%0,%1,%2,%3}, [%4];"
                 : "=f"(v.x), "=f"(v.y), "=f"(v.z), "=f"(v.w) : "l"(p));
    return v;
}

// ---------------------------------------------------------------------------
// Kernel 1: batched per-atom MLP forward + analytic input gradient.
// 256 threads / 8 atoms; 2 atoms per thread. Image rows read via __ldg
// warp-uniform broadcasts (no xs smem stage) -> smem 56.4KB -> 4 CTAs/SM.
// Weights padded-transposed (stride 65, conflict-free both directions).
// ---------------------------------------------------------------------------
__global__ __launch_bounds__(MLP_THREADS) void mlp_kernel(
    const float* __restrict__ image,
    const float* __restrict__ W0,     // [H1, F]   row-major
    const float* __restrict__ W1,     // [H2, H1]  row-major
    const float* __restrict__ Wout)   // [1, H2]
{
    extern __shared__ float sm[];
    float* W0T   = sm;                      // [F][65]
    float* W1T   = W0T + Ff * 65;           // [H1][65]
    float* WoS   = W1T + H1 * 65;           // [64]
    float* h0s   = WoS + 64;                // [TILE][64]
    float* t1s   = h0s + TILE * H1;         // [TILE][64]
    float* t0s   = t1s + TILE * H2;         // [TILE][64]
    float* ePart = t0s + TILE * H1;         // [TILE][2]

    const int t    = threadIdx.x;
    const int base = blockIdx.x * TILE;
    const int p    = t >> 6;
    const int n    = t & 63;
    const int a0   = 2 * p, a1 = 2 * p + 1;

    for (int i = t; i < H1 * Ff; i += MLP_THREADS) {
        int r = i >> 7, f = i & 127;
        W0T[f * 65 + r] = W0[i];
    }
    for (int i = t; i < H2 * H1; i += MLP_THREADS) {
        int j = i >> 6, k = i & 63;
        W1T[k * 65 + j] = W1[i];
    }
    if (t < H2) WoS[t] = Wout[t];
    __syncthreads();

    // phase 1: h0 = sigmoid(x @ W0^T); image read as uniform float4 broadcasts
    {
        const float4* X0 = (const float4*)(image + (size_t)(base + a0) * Ff);
        const float4* X1 = (const float4*)(image + (size_t)(base + a1) * Ff);
        float s0a = 0.f, s0b = 0.f, s1a = 0.f, s1b = 0.f;
#pragma unroll
        for (int f4 = 0; f4 < Ff / 4; f4++) {
            float4 xa = __ldg(X0 + f4);
            float4 xb = __ldg(X1 + f4);
            const int f = f4 * 4;
            float w0 = W0T[(f + 0) * 65 + n];
            float w1 = W0T[(f + 1) * 65 + n];
            float w2 = W0T[(f + 2) * 65 + n];
            float w3 = W0T[(f + 3) * 65 + n];
            s0a = fmaf(xa.x, w0, s0a); s0b = fmaf(xa.y, w1, s0b);
            s0a = fmaf(xa.z, w2, s0a); s0b = fmaf(xa.w, w3, s0b);
            s1a = fmaf(xb.x, w0, s1a); s1b = fmaf(xb.y, w1, s1b);
            s1a = fmaf(xb.z, w2, s1a); s1b = fmaf(xb.w, w3, s1b);
        }
        h0s[a0 * 64 + n] = sigmoidf(s0a + s0b);
        h0s[a1 * 64 + n] = sigmoidf(s1a + s1b);
    }
    __syncthreads();

    // phase 2: h1, t1 = h1(1-h1)*Wout, Ei partials
    {
        const float4* Ha = (const float4*)(h0s + a0 * 64);
        const float4* Hb = (const float4*)(h0s + a1 * 64);
        float s0a = 0.f, s0b = 0.f, s1a = 0.f, s1b = 0.f;
#pragma unroll
        for (int k4 = 0; k4 < H1 / 4; k4++) {
            float4 ha = Ha[k4];
            float4 hb = Hb[k4];
            const int k = k4 * 4;
            float w0 = W1T[(k + 0) * 65 + n];
            float w1 = W1T[(k + 1) * 65 + n];
            float w2 = W1T[(k + 2) * 65 + n];
            float w3 = W1T[(k + 3) * 65 + n];
            s0a = fmaf(ha.x, w0, s0a); s0b = fmaf(ha.y, w1, s0b);
            s0a = fmaf(ha.z, w2, s0a); s0b = fmaf(ha.w, w3, s0b);
            s1a = fmaf(hb.x, w0, s1a); s1b = fmaf(hb.y, w1, s1b);
            s1a = fmaf(hb.z, w2, s1a); s1b = fmaf(hb.w, w3, s1b);
        }
        float wo   = WoS[n];
        float h1_0 = sigmoidf(s0a + s0b);
        float h1_1 = sigmoidf(s1a + s1b);
        t1s[a0 * 64 + n] = h1_0 * (1.f - h1_0) * wo;
        t1s[a1 * 64 + n] = h1_1 * (1.f - h1_1) * wo;
        float e0 = h1_0 * wo, e1 = h1_1 * wo;
#pragma unroll
        for (int off = 16; off > 0; off >>= 1) {
            e0 += __shfl_down_sync(0xffffffffu, e0, off);
            e1 += __shfl_down_sync(0xffffffffu, e1, off);
        }
        if ((n & 31) == 0) {
            int half = n >> 5;
            ePart[a0 * 2 + half] = e0;
            ePart[a1 * 2 + half] = e1;
        }
    }
    __syncthreads();

    // phase 3: g1 = t1 @ W1 ; t0 = h0(1-h0)*g1
    {
        const float4* Ta = (const float4*)(t1s + a0 * 64);
        const float4* Tb = (const float4*)(t1s + a1 * 64);
        float s0a = 0.f, s0b = 0.f, s1a = 0.f, s1b = 0.f;
#pragma unroll
        for (int j4 = 0; j4 < H2 / 4; j4++) {
            float4 ta = Ta[j4];
            float4 tb = Tb[j4];
            const int j = j4 * 4;
            float w0 = W1T[n * 65 + j + 0];
            float w1 = W1T[n * 65 + j + 1];
            float w2 = W1T[n * 65 + j + 2];
            float w3 = W1T[n * 65 + j + 3];
            s0a = fmaf(ta.x, w0, s0a); s0b = fmaf(ta.y, w1, s0b);
            s0a = fmaf(ta.z, w2, s0a); s0b = fmaf(ta.w, w3, s0b);
            s1a = fmaf(tb.x, w0, s1a); s1b = fmaf(tb.y, w1, s1b);
            s1a = fmaf(tb.z, w2, s1a); s1b = fmaf(tb.w, w3, s1b);
        }
        float h00 = h0s[a0 * 64 + n];
        float h01 = h0s[a1 * 64 + n];
        t0s[a0 * 64 + n] = h00 * (1.f - h00) * (s0a + s0b);
        t0s[a1 * 64 + n] = h01 * (1.f - h01) * (s1a + s1b);
        if (n == 0) {
            Ei_buf[base + a0] = ePart[a0 * 2] + ePart[a0 * 2 + 1];
            Ei_buf[base + a1] = ePart[a1 * 2] + ePart[a1 * 2 + 1];
        }
    }
    __syncthreads();

    // phase 4: g[f] = sum_k t0[k] * W0[k][f]
    {
        const int f0 = n, f1 = n + 64;
        const float4* Pa = (const float4*)(t0s + a0 * 64);
        const float4* Pb = (const float4*)(t0s + a1 * 64);
        float g00 = 0.f, g01 = 0.f, g10 = 0.f, g11 = 0.f;
#pragma unroll
        for (int k4 = 0; k4 < H1 / 4; k4++) {
            float4 ta = Pa[k4];
            float4 tb = Pb[k4];
            const int k = k4 * 4;
#pragma unroll
            for (int u = 0; u < 4; u++) {
                float w0 = W0T[f0 * 65 + k + u];
                float w1 = W0T[f1 * 65 + k + u];
                float va = (u == 0) ? ta.x : (u == 1) ? ta.y : (u == 2) ? ta.z : ta.w;
                float vb = (u == 0) ? tb.x : (u == 1) ? tb.y : (u == 2) ? tb.z : tb.w;
                g00 = fmaf(va, w0, g00);
                g01 = fmaf(va, w1, g01);
                g10 = fmaf(vb, w0, g10);
                g11 = fmaf(vb, w1, g11);
            }
        }
        float* go0 = g_buf + (size_t)(base + a0) * Ff;
        float* go1 = g_buf + (size_t)(base + a1) * Ff;
        go0[f0] = g00; go0[f1] = g01;
        go1[f0] = g10; go1[f1] = g11;
    }
}

// ---------------------------------------------------------------------------
// Kernel 2: force — chunked-gather pipeline, single launch over all atoms.
// 4 cp.async commit groups (16 rows each); progressive wait_group; dfeat via
// ld.global.cs (read-once stream must not evict L2-resident g_buf).
// ---------------------------------------------------------------------------
__global__ __launch_bounds__(FBLK) void force_kernel(
    const int*   __restrict__ neighbor,   // [B*N, M]
    const float* __restrict__ dfeat,      // [B*N, M, F, 3]
    float*       __restrict__ out_force)  // [B*N, 3]
{
    const int atom = blockIdx.x;
    const int b    = atom >> 11;            // N = 2048
    const int t    = threadIdx.x;

    __shared__ float sg[Mm * Ff];            // 32 KB gathered+masked g rows
    __shared__ float wsum[12][3];

    {
        float4*       sg4 = (float4*)sg;
        const float4* g4  = (const float4*)g_buf;
        const float4* z4  = (const float4*)g_zero;
        const int*    nb  = neighbor + atom * Mm;
#pragma unroll
        for (int c = 0; c < 4; c++) {
            for (int i = c * 512 + t; i < (c + 1) * 512; i += FBLK) {
                int m  = i >> 5;
                int f4 = i & 31;
                int nei = __ldg(nb + m);
                const float4* src = (nei > 0)
                    ? g4 + ((size_t)(b * Nn + nei - 1)) * (Ff / 4) + f4
                    : z4 + f4;
                cp_async16(sg4 + i, src);
            }
            asm volatile("cp.async.commit_group;");
        }
    }

    const int r4  = t % 96;
    const int m0  = t / 96;
    const int cse = r4 % 3;
    const int f0  = (4 * r4) / 3;

    const float4* dp = (const float4*)(dfeat + (size_t)atom * (Mm * Ff * 3)) + t;

    float A0 = 0.f, A1 = 0.f, A2 = 0.f;      // A_k holds c = (cse+k)%3
#pragma unroll
    for (int c = 0; c < 4; c++) {
        if (c == 0)      asm volatile("cp.async.wait_group 3;" ::: "memory");
        else if (c == 1) asm volatile("cp.async.wait_group 2;" ::: "memory");
        else if (c == 2) asm volatile("cp.async.wait_group 1;" ::: "memory");
        else             asm volatile("cp.async.wait_group 0;" ::: "memory");
        __syncthreads();
#pragma unroll
        for (int q = 0; q < 4; q++) {
            const int it = c * 4 + q;
            const int m  = m0 + 4 * it;
            float4 v = ldcs4(dp + (size_t)it * 384);
            float s0 = sg[m * Ff + f0];
            float s1 = sg[m * Ff + f0 + 1];
            float sy = (cse == 2) ? s1 : s0;
            float sz = (cse == 0) ? s0 : s1;
            A0 = fmaf(v.x, s0, A0);
            A1 = fmaf(v.y, sy, A1);
            A2 = fmaf(v.z, sz, A2);
            A0 = fmaf(v.w, s1, A0);
        }
    }
    float c0 = (cse == 0) ? A0 : (cse == 1) ? A2 : A1;
    float c1 = (cse == 0) ? A1 : (cse == 1) ? A0 : A2;
    float c2 = (cse == 0) ? A2 : (cse == 1) ? A1 : A0;

#pragma unroll
    for (int off = 16; off > 0; off >>= 1) {
        c0 += __shfl_down_sync(0xffffffffu, c0, off);
        c1 += __shfl_down_sync(0xffffffffu, c1, off);
        c2 += __shfl_down_sync(0xffffffffu, c2, off);
    }
    const int w = t >> 5;
    if ((t & 31) == 0) { wsum[w][0] = c0; wsum[w][1] = c1; wsum[w][2] = c2; }
    __syncthreads();

    if (t < 3) {
        float s = 0.f;
#pragma unroll
        for (int w2 = 0; w2 < 12; w2++) s += wsum[w2][t];
        out_force[atom * 3 + t] = s * 1e10f;
    }
}

// ---------------------------------------------------------------------------
// Kernel 3: deterministic Etot = sum_n Ei  (double accumulation)
// ---------------------------------------------------------------------------
__global__ __launch_bounds__(256) void etot_kernel(float* __restrict__ out)
{
    const int b = blockIdx.x;
    const int t = threadIdx.x;
    __shared__ double sd[256];

    double s = 0.0;
    for (int n = t; n < Nn; n += 256) s += (double)Ei_buf[b * Nn + n];
    sd[t] = s;
    __syncthreads();
#pragma unroll
    for (int k = 128; k > 0; k >>= 1) {
        if (t < k) sd[t] += sd[t + k];
        __syncthreads();
    }
    if (t == 0) out[b] = (float)sd[0];
}

// ---------------------------------------------------------------------------
// Launch: single mlp (both batches) -> single force; etot on side stream.
// ---------------------------------------------------------------------------
extern "C" void kernel_launch(void* const* d_in, const int* in_sizes, int n_in,
                              void* d_out, int out_size)
{
    const float* image    = (const float*)d_in[0];
    const float* dfeat    = (const float*)d_in[1];
    const int*   neighbor = (const int*)  d_in[2];
    const float* W0       = (const float*)d_in[5];
    const float* W1       = (const float*)d_in[6];
    const float* Wout     = (const float*)d_in[7];
    float* out = (float*)d_out;

    const int mlp_smem = (Ff * 65 + H1 * 65 + 64 + 3 * TILE * 64 + 2 * TILE)
                       * (int)sizeof(float);   // 56,384 B -> 4 CTAs/SM

    static cudaStream_t s2 = nullptr;
    static cudaEvent_t  e0, eE;
    if (!s2) {
        cudaStreamCreateWithFlags(&s2, cudaStreamNonBlocking);
        cudaEventCreateWithFlags(&e0, cudaEventDisableTiming);
        cudaEventCreateWithFlags(&eE, cudaEventDisableTiming);
        cudaFuncSetAttribute(mlp_kernel, cudaFuncAttributeMaxDynamicSharedMemorySize, mlp_smem);
    }

    // stream 0: mlp (both batches) -> force (all atoms)
    mlp_kernel<<<(Bb * Nn) / TILE, MLP_THREADS, mlp_smem>>>(image, W0, W1, Wout);
    cudaEventRecord(e0, 0);
    force_kernel<<<Bb * Nn, FBLK>>>(neighbor, dfeat, out + 2);

    // side stream: etot overlaps force
    cudaStreamWaitEvent(s2, e0, 0);
    etot_kernel<<<Bb, 256, 0, s2>>>(out);
    cudaEventRecord(eE, s2);

    cudaStreamWaitEvent(0, eE, 0);
}

// round 14
// speedup vs baseline: 1.1152x; 1.0427x over previous
#include <cuda_runtime.h>
#include <cstdint>

#define Bb 2
#define Nn 2048
#define Mm 64
#define Ff 128
#define H1 64
#define H2 64
#define TILE 16         // atoms per MLP block (8 warps x 2 atoms)
#define MLP_THREADS 256
#define FBLK 384        // force threads per atom block

// scratch (allocation-free rule: __device__ globals; zero-initialized)
__device__ float g_buf[Bb * Nn * Ff];   // input-gradient per atom  [B*N, F]
__device__ float Ei_buf[Bb * Nn];       // per-atom energy
__device__ float g_zero[Ff];            // stays all-zero (pad-neighbor source)

__device__ __forceinline__ float sigmoidf(float z) {
    return 1.f / (1.f + __expf(-z));
}

__device__ __forceinline__ void cp_async16(void* dst_smem, const void* src_gmem) {
    unsigned int d = (unsigned int)__cvta_generic_to_shared(dst_smem);
    asm volatile("cp.async.ca.shared.global [%0], [%1], 16;" :: "r"(d), "l"(src_gmem));
}

__device__ __forceinline__ float4 ldcs4(const float4* p) {
    float4 v;
    asm volatile("ld.global.cs.v4.f32 {%0,%1,%2,%3}, [%4];"
                 : "=f"(v.x), "=f"(v.y), "=f"(v.z), "=f"(v.w) : "l"(p));
    return v;
}

// ---------------------------------------------------------------------------
// Kernel 1: warp-autonomous MLP. Each warp owns 2 atoms end-to-end; lane
// handles neurons n=lane and n+32 (weights reused across the 2 atoms).
// After the weight-staging __syncthreads, NO block barriers: per-warp smem
// activation slices + __syncwarp only. Weights padded-transposed (stride 65).
// ---------------------------------------------------------------------------
__global__ __launch_bounds__(MLP_THREADS) void mlp_kernel(
    const float* __restrict__ image,
    const float* __restrict__ W0,     // [H1, F]   row-major
    const float* __restrict__ W1,     // [H2, H1]  row-major
    const float* __restrict__ Wout)   // [1, H2]
{
    extern __shared__ float sm[];
    float* W0T  = sm;                       // [F][65]:  W0T[f*65+n] = W0[n][f]
    float* W1T  = W0T + Ff * 65;            // [H1][65]: W1T[k*65+j] = W1[j][k]
    float* WoS  = W1T + H1 * 65;            // [64]
    float* wbuf = WoS + 64;                 // 8 warps x 384 floats

    const int t    = threadIdx.x;
    const int warp = t >> 5;
    const int lane = t & 31;
    const int base = blockIdx.x * TILE;
    const int aA   = base + 2 * warp;
    const int aB   = aA + 1;
    const int n0   = lane, n1 = lane + 32;

    // ---- stage weights (coalesced, conflict-free) ----
    for (int i = t; i < H1 * Ff; i += MLP_THREADS) {
        int r = i >> 7, f = i & 127;
        W0T[f * 65 + r] = W0[i];
    }
    for (int i = t; i < H2 * H1; i += MLP_THREADS) {
        int j = i >> 6, k = i & 63;
        W1T[k * 65 + j] = W1[i];
    }
    if (t < H2) WoS[t] = Wout[t];
    __syncthreads();                        // the ONLY block barrier

    float* hA  = wbuf + warp * 384;
    float* hB  = hA + 64;
    float* t1A = hB + 64;
    float* t1B = t1A + 64;
    float* t0A = t1B + 64;
    float* t0B = t0A + 64;

    // ---- phase 1: h0 = sigmoid(x @ W0^T) ----
    float h00, h01, h10, h11;               // sigmoid outputs kept in regs
    {
        const float4* XA = (const float4*)(image + (size_t)aA * Ff);
        const float4* XB = (const float4*)(image + (size_t)aB * Ff);
        float aA0 = 0.f, aA1 = 0.f, aB0 = 0.f, aB1 = 0.f;
        float bA0 = 0.f, bA1 = 0.f, bB0 = 0.f, bB1 = 0.f;
#pragma unroll
        for (int f4 = 0; f4 < Ff / 4; f4++) {
            float4 xa = __ldg(XA + f4);
            float4 xb = __ldg(XB + f4);
            const int f = f4 * 4;
            float w00 = W0T[(f + 0) * 65 + n0], w10 = W0T[(f + 0) * 65 + n1];
            float w01 = W0T[(f + 1) * 65 + n0], w11 = W0T[(f + 1) * 65 + n1];
            float w02 = W0T[(f + 2) * 65 + n0], w12 = W0T[(f + 2) * 65 + n1];
            float w03 = W0T[(f + 3) * 65 + n0], w13 = W0T[(f + 3) * 65 + n1];
            aA0 = fmaf(xa.x, w00, aA0); bA0 = fmaf(xa.y, w01, bA0);
            aA0 = fmaf(xa.z, w02, aA0); bA0 = fmaf(xa.w, w03, bA0);
            aA1 = fmaf(xa.x, w10, aA1); bA1 = fmaf(xa.y, w11, bA1);
            aA1 = fmaf(xa.z, w12, aA1); bA1 = fmaf(xa.w, w13, bA1);
            aB0 = fmaf(xb.x, w00, aB0); bB0 = fmaf(xb.y, w01, bB0);
            aB0 = fmaf(xb.z, w02, aB0); bB0 = fmaf(xb.w, w03, bB0);
            aB1 = fmaf(xb.x, w10, aB1); bB1 = fmaf(xb.y, w11, bB1);
            aB1 = fmaf(xb.z, w12, aB1); bB1 = fmaf(xb.w, w13, bB1);
        }
        h00 = sigmoidf(aA0 + bA0);          // atom A, neuron n0
        h01 = sigmoidf(aA1 + bA1);          // atom A, neuron n1
        h10 = sigmoidf(aB0 + bB0);          // atom B, neuron n0
        h11 = sigmoidf(aB1 + bB1);
        hA[n0] = h00; hA[n1] = h01;
        hB[n0] = h10; hB[n1] = h11;
    }
    __syncwarp();

    // ---- phase 2: h1, t1 = h1(1-h1)*Wout, Ei ----
    {
        float aA0 = 0.f, aA1 = 0.f, aB0 = 0.f, aB1 = 0.f;
        float bA0 = 0.f, bA1 = 0.f, bB0 = 0.f, bB1 = 0.f;
#pragma unroll
        for (int k4 = 0; k4 < H1 / 4; k4++) {
            float4 ha = *(const float4*)(hA + k4 * 4);   // warp-broadcast
            float4 hb = *(const float4*)(hB + k4 * 4);
            const int k = k4 * 4;
            float w00 = W1T[(k + 0) * 65 + n0], w10 = W1T[(k + 0) * 65 + n1];
            float w01 = W1T[(k + 1) * 65 + n0], w11 = W1T[(k + 1) * 65 + n1];
            float w02 = W1T[(k + 2) * 65 + n0], w12 = W1T[(k + 2) * 65 + n1];
            float w03 = W1T[(k + 3) * 65 + n0], w13 = W1T[(k + 3) * 65 + n1];
            aA0 = fmaf(ha.x, w00, aA0); bA0 = fmaf(ha.y, w01, bA0);
            aA0 = fmaf(ha.z, w02, aA0); bA0 = fmaf(ha.w, w03, bA0);
            aA1 = fmaf(ha.x, w10, aA1); bA1 = fmaf(ha.y, w11, bA1);
            aA1 = fmaf(ha.z, w12, aA1); bA1 = fmaf(ha.w, w13, bA1);
            aB0 = fmaf(hb.x, w00, aB0); bB0 = fmaf(hb.y, w01, bB0);
            aB0 = fmaf(hb.z, w02, aB0); bB0 = fmaf(hb.w, w03, bB0);
            aB1 = fmaf(hb.x, w10, aB1); bB1 = fmaf(hb.y, w11, bB1);
            aB1 = fmaf(hb.z, w12, aB1); bB1 = fmaf(hb.w, w13, bB1);
        }
        float wo0 = WoS[n0], wo1 = WoS[n1];
        float hA0 = sigmoidf(aA0 + bA0), hA1 = sigmoidf(aA1 + bA1);
        float hB0 = sigmoidf(aB0 + bB0), hB1 = sigmoidf(aB1 + bB1);
        t1A[n0] = hA0 * (1.f - hA0) * wo0;
        t1A[n1] = hA1 * (1.f - hA1) * wo1;
        t1B[n0] = hB0 * (1.f - hB0) * wo0;
        t1B[n1] = hB1 * (1.f - hB1) * wo1;
        float eA = fmaf(hA0, wo0, hA1 * wo1);
        float eB = fmaf(hB0, wo0, hB1 * wo1);
#pragma unroll
        for (int off = 16; off > 0; off >>= 1) {
            eA += __shfl_down_sync(0xffffffffu, eA, off);
            eB += __shfl_down_sync(0xffffffffu, eB, off);
        }
        if (lane == 0) {
            Ei_buf[aA] = eA;
            Ei_buf[aB] = eB;
        }
    }
    __syncwarp();

    // ---- phase 3: g1 = t1 @ W1 ; t0 = h0(1-h0)*g1 ----
    {
        float aA0 = 0.f, aA1 = 0.f, aB0 = 0.f, aB1 = 0.f;
        float bA0 = 0.f, bA1 = 0.f, bB0 = 0.f, bB1 = 0.f;
#pragma unroll
        for (int j4 = 0; j4 < H2 / 4; j4++) {
            float4 ta = *(const float4*)(t1A + j4 * 4);  // warp-broadcast
            float4 tb = *(const float4*)(t1B + j4 * 4);
            const int j = j4 * 4;
            float w00 = W1T[n0 * 65 + j + 0], w10 = W1T[n1 * 65 + j + 0];
            float w01 = W1T[n0 * 65 + j + 1], w11 = W1T[n1 * 65 + j + 1];
            float w02 = W1T[n0 * 65 + j + 2], w12 = W1T[n1 * 65 + j + 2];
            float w03 = W1T[n0 * 65 + j + 3], w13 = W1T[n1 * 65 + j + 3];
            aA0 = fmaf(ta.x, w00, aA0); bA0 = fmaf(ta.y, w01, bA0);
            aA0 = fmaf(ta.z, w02, aA0); bA0 = fmaf(ta.w, w03, bA0);
            aA1 = fmaf(ta.x, w10, aA1); bA1 = fmaf(ta.y, w11, bA1);
            aA1 = fmaf(ta.z, w12, aA1); bA1 = fmaf(ta.w, w13, bA1);
            aB0 = fmaf(tb.x, w00, aB0); bB0 = fmaf(tb.y, w01, bB0);
            aB0 = fmaf(tb.z, w02, aB0); bB0 = fmaf(tb.w, w03, bB0);
            aB1 = fmaf(tb.x, w10, aB1); bB1 = fmaf(tb.y, w11, bB1);
            aB1 = fmaf(tb.z, w12, aB1); bB1 = fmaf(tb.w, w13, bB1);
        }
        t0A[n0] = h00 * (1.f - h00) * (aA0 + bA0);
        t0A[n1] = h01 * (1.f - h01) * (aA1 + bA1);
        t0B[n0] = h10 * (1.f - h10) * (aB0 + bB0);
        t0B[n1] = h11 * (1.f - h11) * (aB1 + bB1);
    }
    __syncwarp();

    // ---- phase 4: g[f] = sum_k t0[k] * W0[k][f]; lane owns f = lane+32u ----
    {
        const int f0 = lane, f1 = lane + 32, f2 = lane + 64, f3 = lane + 96;
        float gA0 = 0.f, gA1 = 0.f, gA2 = 0.f, gA3 = 0.f;
        float gB0 = 0.f, gB1 = 0.f, gB2 = 0.f, gB3 = 0.f;
#pragma unroll
        for (int k4 = 0; k4 < H1 / 4; k4++) {
            float4 ta = *(const float4*)(t0A + k4 * 4);  // warp-broadcast
            float4 tb = *(const float4*)(t0B + k4 * 4);
#pragma unroll
            for (int u = 0; u < 4; u++) {
                const int k = k4 * 4 + u;
                float w0 = W0T[f0 * 65 + k];
                float w1 = W0T[f1 * 65 + k];
                float w2 = W0T[f2 * 65 + k];
                float w3 = W0T[f3 * 65 + k];
                float va = (u == 0) ? ta.x : (u == 1) ? ta.y : (u == 2) ? ta.z : ta.w;
                float vb = (u == 0) ? tb.x : (u == 1) ? tb.y : (u == 2) ? tb.z : tb.w;
                gA0 = fmaf(va, w0, gA0); gA1 = fmaf(va, w1, gA1);
                gA2 = fmaf(va, w2, gA2); gA3 = fmaf(va, w3, gA3);
                gB0 = fmaf(vb, w0, gB0); gB1 = fmaf(vb, w1, gB1);
                gB2 = fmaf(vb, w2, gB2); gB3 = fmaf(vb, w3, gB3);
            }
        }
        float* goA = g_buf + (size_t)aA * Ff;
        float* goB = g_buf + (size_t)aB * Ff;
        goA[f0] = gA0; goA[f1] = gA1; goA[f2] = gA2; goA[f3] = gA3;
        goB[f0] = gB0; goB[f1] = gB1; goB[f2] = gB2; goB[f3] = gB3;
    }
}

// ---------------------------------------------------------------------------
// Kernel 2: force — chunked-gather pipeline, single launch over all atoms.
// 4 cp.async commit groups (16 rows each); progressive wait_group; dfeat via
// ld.global.cs (read-once stream must not evict L2-resident g_buf).
// ---------------------------------------------------------------------------
__global__ __launch_bounds__(FBLK) void force_kernel(
    const int*   __restrict__ neighbor,   // [B*N, M]
    const float* __restrict__ dfeat,      // [B*N, M, F, 3]
    float*       __restrict__ out_force)  // [B*N, 3]
{
    const int atom = blockIdx.x;
    const int b    = atom >> 11;            // N = 2048
    const int t    = threadIdx.x;

    __shared__ float sg[Mm * Ff];            // 32 KB gathered+masked g rows
    __shared__ float wsum[12][3];

    {
        float4*       sg4 = (float4*)sg;
        const float4* g4  = (const float4*)g_buf;
        const float4* z4  = (const float4*)g_zero;
        const int*    nb  = neighbor + atom * Mm;
#pragma unroll
        for (int c = 0; c < 4; c++) {
            for (int i = c * 512 + t; i < (c + 1) * 512; i += FBLK) {
                int m  = i >> 5;
                int f4 = i & 31;
                int nei = __ldg(nb + m);
                const float4* src = (nei > 0)
                    ? g4 + ((size_t)(b * Nn + nei - 1)) * (Ff / 4) + f4
                    : z4 + f4;
                cp_async16(sg4 + i, src);
            }
            asm volatile("cp.async.commit_group;");
        }
    }

    const int r4  = t % 96;
    const int m0  = t / 96;
    const int cse = r4 % 3;
    const int f0  = (4 * r4) / 3;

    const float4* dp = (const float4*)(dfeat + (size_t)atom * (Mm * Ff * 3)) + t;

    float A0 = 0.f, A1 = 0.f, A2 = 0.f;      // A_k holds c = (cse+k)%3
#pragma unroll
    for (int c = 0; c < 4; c++) {
        if (c == 0)      asm volatile("cp.async.wait_group 3;" ::: "memory");
        else if (c == 1) asm volatile("cp.async.wait_group 2;" ::: "memory");
        else if (c == 2) asm volatile("cp.async.wait_group 1;" ::: "memory");
        else             asm volatile("cp.async.wait_group 0;" ::: "memory");
        __syncthreads();
#pragma unroll
        for (int q = 0; q < 4; q++) {
            const int it = c * 4 + q;
            const int m  = m0 + 4 * it;
            float4 v = ldcs4(dp + (size_t)it * 384);
            float s0 = sg[m * Ff + f0];
            float s1 = sg[m * Ff + f0 + 1];
            float sy = (cse == 2) ? s1 : s0;
            float sz = (cse == 0) ? s0 : s1;
            A0 = fmaf(v.x, s0, A0);
            A1 = fmaf(v.y, sy, A1);
            A2 = fmaf(v.z, sz, A2);
            A0 = fmaf(v.w, s1, A0);
        }
    }
    float c0 = (cse == 0) ? A0 : (cse == 1) ? A2 : A1;
    float c1 = (cse == 0) ? A1 : (cse == 1) ? A0 : A2;
    float c2 = (cse == 0) ? A2 : (cse == 1) ? A1 : A0;

#pragma unroll
    for (int off = 16; off > 0; off >>= 1) {
        c0 += __shfl_down_sync(0xffffffffu, c0, off);
        c1 += __shfl_down_sync(0xffffffffu, c1, off);
        c2 += __shfl_down_sync(0xffffffffu, c2, off);
    }
    const int w = t >> 5;
    if ((t & 31) == 0) { wsum[w][0] = c0; wsum[w][1] = c1; wsum[w][2] = c2; }
    __syncthreads();

    if (t < 3) {
        float s = 0.f;
#pragma unroll
        for (int w2 = 0; w2 < 12; w2++) s += wsum[w2][t];
        out_force[atom * 3 + t] = s * 1e10f;
    }
}

// ---------------------------------------------------------------------------
// Kernel 3: deterministic Etot = sum_n Ei  (double accumulation)
// ---------------------------------------------------------------------------
__global__ __launch_bounds__(256) void etot_kernel(float* __restrict__ out)
{
    const int b = blockIdx.x;
    const int t = threadIdx.x;
    __shared__ double sd[256];

    double s = 0.0;
    for (int n = t; n < Nn; n += 256) s += (double)Ei_buf[b * Nn + n];
    sd[t] = s;
    __syncthreads();
#pragma unroll
    for (int k = 128; k > 0; k >>= 1) {
        if (t < k) sd[t] += sd[t + k];
        __syncthreads();
    }
    if (t == 0) out[b] = (float)sd[0];
}

// ---------------------------------------------------------------------------
// Launch: single mlp (both batches) -> single force; etot on side stream.
// ---------------------------------------------------------------------------
extern "C" void kernel_launch(void* const* d_in, const int* in_sizes, int n_in,
                              void* d_out, int out_size)
{
    const float* image    = (const float*)d_in[0];
    const float* dfeat    = (const float*)d_in[1];
    const int*   neighbor = (const int*)  d_in[2];
    const float* W0       = (const float*)d_in[5];
    const float* W1       = (const float*)d_in[6];
    const float* Wout     = (const float*)d_in[7];
    float* out = (float*)d_out;

    const int mlp_smem = (Ff * 65 + H1 * 65 + 64 + 8 * 384) * (int)sizeof(float); // 62,464 B

    static cudaStream_t s2 = nullptr;
    static cudaEvent_t  e0, eE;
    if (!s2) {
        cudaStreamCreateWithFlags(&s2, cudaStreamNonBlocking);
        cudaEventCreateWithFlags(&e0, cudaEventDisableTiming);
        cudaEventCreateWithFlags(&eE, cudaEventDisableTiming);
        cudaFuncSetAttribute(mlp_kernel, cudaFuncAttributeMaxDynamicSharedMemorySize, mlp_smem);
    }

    // stream 0: mlp (both batches) -> force (all atoms)
    mlp_kernel<<<(Bb * Nn) / TILE, MLP_THREADS, mlp_smem>>>(image, W0, W1, Wout);
    cudaEventRecord(e0, 0);
    force_kernel<<<Bb * Nn, FBLK>>>(neighbor, dfeat, out + 2);

    // side stream: etot overlaps force
    cudaStreamWaitEvent(s2, e0, 0);
    etot_kernel<<<Bb, 256, 0, s2>>>(out);
    cudaEventRecord(eE, s2);

    cudaStreamWaitEvent(0, eE, 0);
}